// round 2
// baseline (speedup 1.0000x reference)
#include <cuda_runtime.h>

#define NSTATE 1024
#define NHEAD  16
#define HDIM   64
#define TMAX   6144

// Scratch (device globals: allocation-free rule)
__device__ float g_q[TMAX * NSTATE];
__device__ float g_k[TMAX * NSTATE];
__device__ float g_v[TMAX * NSTATE];
__device__ float g_ctx[TMAX * NSTATE];

// ---------------------------------------------------------------------------
// SGEMM NT: C[M,N] = A[M,K] @ W[N,K]^T (+ bias). BM=BN=128, BK=16, 256 thr,
// 8x8 per-thread tile. Assumes M%128==0, N%128==0, K%16==0 (true here).
// ---------------------------------------------------------------------------
__device__ __forceinline__ void sgemm_body(const float* __restrict__ A,
                                           const float* __restrict__ W,
                                           const float* __restrict__ bias,
                                           float* __restrict__ C,
                                           int M, int N, int K)
{
    __shared__ float As[16][128];
    __shared__ float Bs[16][128];

    const int tid = threadIdx.x;
    const int tx = tid & 15;        // N direction
    const int ty = tid >> 4;        // M direction
    const int bm = blockIdx.y * 128;
    const int bn = blockIdx.x * 128;

    const int lrow = tid >> 1;      // 0..127
    const int lk   = (tid & 1) * 8; // 0 or 8

    const float* Ag = A + (size_t)(bm + lrow) * K + lk;
    const float* Wg = W + (size_t)(bn + lrow) * K + lk;

    float acc[8][8];
#pragma unroll
    for (int i = 0; i < 8; i++)
#pragma unroll
        for (int j = 0; j < 8; j++) acc[i][j] = 0.f;

    for (int k0 = 0; k0 < K; k0 += 16) {
        float4 a0 = *(const float4*)(Ag + k0);
        float4 a1 = *(const float4*)(Ag + k0 + 4);
        float4 w0 = *(const float4*)(Wg + k0);
        float4 w1 = *(const float4*)(Wg + k0 + 4);

        __syncthreads();  // previous iteration's reads done
        As[lk + 0][lrow] = a0.x; As[lk + 1][lrow] = a0.y;
        As[lk + 2][lrow] = a0.z; As[lk + 3][lrow] = a0.w;
        As[lk + 4][lrow] = a1.x; As[lk + 5][lrow] = a1.y;
        As[lk + 6][lrow] = a1.z; As[lk + 7][lrow] = a1.w;
        Bs[lk + 0][lrow] = w0.x; Bs[lk + 1][lrow] = w0.y;
        Bs[lk + 2][lrow] = w0.z; Bs[lk + 3][lrow] = w0.w;
        Bs[lk + 4][lrow] = w1.x; Bs[lk + 5][lrow] = w1.y;
        Bs[lk + 6][lrow] = w1.z; Bs[lk + 7][lrow] = w1.w;
        __syncthreads();

#pragma unroll
        for (int kk = 0; kk < 16; kk++) {
            float a[8], b[8];
            *(float4*)&a[0] = *(const float4*)&As[kk][ty * 8];
            *(float4*)&a[4] = *(const float4*)&As[kk][ty * 8 + 4];
            *(float4*)&b[0] = *(const float4*)&Bs[kk][tx * 8];
            *(float4*)&b[4] = *(const float4*)&Bs[kk][tx * 8 + 4];
#pragma unroll
            for (int i = 0; i < 8; i++)
#pragma unroll
                for (int j = 0; j < 8; j++)
                    acc[i][j] = fmaf(a[i], b[j], acc[i][j]);
        }
    }

    float bb[8];
#pragma unroll
    for (int j = 0; j < 8; j++) bb[j] = bias ? bias[bn + tx * 8 + j] : 0.f;

#pragma unroll
    for (int i = 0; i < 8; i++) {
        const int row = bm + ty * 8 + i;
        float* Cp = C + (size_t)row * N + bn + tx * 8;
        float4 c0, c1;
        c0.x = acc[i][0] + bb[0]; c0.y = acc[i][1] + bb[1];
        c0.z = acc[i][2] + bb[2]; c0.w = acc[i][3] + bb[3];
        c1.x = acc[i][4] + bb[4]; c1.y = acc[i][5] + bb[5];
        c1.z = acc[i][6] + bb[6]; c1.w = acc[i][7] + bb[7];
        *(float4*)(Cp)     = c0;
        *(float4*)(Cp + 4) = c1;
    }
}

__global__ __launch_bounds__(256)
void qkv_kernel(const float* __restrict__ x,
                const float* __restrict__ Wq, const float* __restrict__ bq,
                const float* __restrict__ Wk,
                const float* __restrict__ Wv, const float* __restrict__ bv,
                int M)
{
    if (blockIdx.z == 0)       sgemm_body(x, Wq, bq,      g_q, M, NSTATE, NSTATE);
    else if (blockIdx.z == 1)  sgemm_body(x, Wk, nullptr, g_k, M, NSTATE, NSTATE);
    else                       sgemm_body(x, Wv, bv,      g_v, M, NSTATE, NSTATE);
}

__global__ __launch_bounds__(256)
void oproj_kernel(const float* __restrict__ Wo, const float* __restrict__ bo,
                  float* __restrict__ out, int M)
{
    sgemm_body(g_ctx, Wo, bo, out, M, NSTATE, NSTATE);
}

// ---------------------------------------------------------------------------
// Flash attention: one CTA per (64-query tile, head). Online softmax over
// 64-key tiles. Non-causal, ragged sequences via cu_seqlens.
// 256 threads: tx=tid&15 (key/dim cols, 4 each), ty=tid>>4 (query rows, 4 each)
// ---------------------------------------------------------------------------
__global__ __launch_bounds__(256)
void attn_kernel(const int* __restrict__ cu, int nseq)
{
    extern __shared__ float sm[];
    float (*Qs)[65] = (float(*)[65])(sm);
    float (*Ks)[65] = (float(*)[65])(sm + 64 * 65);
    float (*Vs)[65] = (float(*)[65])(sm + 2 * 64 * 65);
    float (*Ps)[65] = (float(*)[65])(sm + 3 * 64 * 65);

    const int h = blockIdx.y;

    // map blockIdx.x -> (sequence, query tile)
    int s0 = 0, L = 0, q0 = 0, found = 0;
    {
        int acct = 0;
        const int gt = blockIdx.x;
        for (int b = 0; b < nseq; b++) {
            const int s = cu[b], e = cu[b + 1];
            const int Lb = e - s;
            const int nt = (Lb + 63) >> 6;
            if (gt < acct + nt) { s0 = s; L = Lb; q0 = s + (gt - acct) * 64; found = 1; break; }
            acct += nt;
        }
    }
    if (!found) return;

    const int tid = threadIdx.x;
    const int tx = tid & 15, ty = tid >> 4;
    const int qrows = min(64, s0 + L - q0);

    // load Q tile, fold in softmax scale 1/sqrt(64)
#pragma unroll
    for (int it = 0; it < 16; it++) {
        const int idx = tid + it * 256;
        const int r = idx >> 6, c = idx & 63;
        Qs[r][c] = (r < qrows) ? g_q[(size_t)(q0 + r) * NSTATE + h * HDIM + c] * 0.125f : 0.f;
    }

    float m_i[4], l_i[4], o[4][4];
#pragma unroll
    for (int i = 0; i < 4; i++) {
        m_i[i] = -1e30f; l_i[i] = 0.f;
#pragma unroll
        for (int j = 0; j < 4; j++) o[i][j] = 0.f;
    }

    const int nkt = (L + 63) >> 6;
    for (int kt = 0; kt < nkt; kt++) {
        const int kbase = kt * 64;
        const int kc = min(64, L - kbase);

        __syncthreads();  // also covers Q-load on first iter; protects Ps/Vs reuse
#pragma unroll
        for (int it = 0; it < 16; it++) {
            const int idx = tid + it * 256;
            const int r = idx >> 6, c = idx & 63;
            const bool ok = (r < kc);
            const size_t g = (size_t)(s0 + kbase + r) * NSTATE + h * HDIM + c;
            Ks[r][c] = ok ? g_k[g] : 0.f;
            Vs[r][c] = ok ? g_v[g] : 0.f;
        }
        __syncthreads();

        // S = Q K^T (scale already in Q)
        float s[4][4];
#pragma unroll
        for (int i = 0; i < 4; i++)
#pragma unroll
            for (int j = 0; j < 4; j++) s[i][j] = 0.f;

#pragma unroll 16
        for (int d = 0; d < 64; d++) {
            float a[4], b[4];
#pragma unroll
            for (int i = 0; i < 4; i++) a[i] = Qs[ty * 4 + i][d];
#pragma unroll
            for (int j = 0; j < 4; j++) b[j] = Ks[tx * 4 + j][d];
#pragma unroll
            for (int i = 0; i < 4; i++)
#pragma unroll
                for (int j = 0; j < 4; j++)
                    s[i][j] = fmaf(a[i], b[j], s[i][j]);
        }

        if (kc < 64) {
#pragma unroll
            for (int j = 0; j < 4; j++)
                if (tx * 4 + j >= kc) {
#pragma unroll
                    for (int i = 0; i < 4; i++) s[i][j] = -1e30f;
                }
        }

        // online softmax (row stats all-reduced over the 16 tx lanes)
#pragma unroll
        for (int i = 0; i < 4; i++) {
            float mt = fmaxf(fmaxf(s[i][0], s[i][1]), fmaxf(s[i][2], s[i][3]));
#pragma unroll
            for (int msk = 1; msk < 16; msk <<= 1)
                mt = fmaxf(mt, __shfl_xor_sync(0xffffffffu, mt, msk));
            const float mn = fmaxf(m_i[i], mt);
            const float alpha = __expf(m_i[i] - mn);
            float r = 0.f;
#pragma unroll
            for (int j = 0; j < 4; j++) { s[i][j] = __expf(s[i][j] - mn); r += s[i][j]; }
#pragma unroll
            for (int msk = 1; msk < 16; msk <<= 1)
                r += __shfl_xor_sync(0xffffffffu, r, msk);
            l_i[i] = l_i[i] * alpha + r;
            m_i[i] = mn;
#pragma unroll
            for (int j = 0; j < 4; j++) o[i][j] *= alpha;
        }

        // write P, then O += P @ V
#pragma unroll
        for (int i = 0; i < 4; i++)
#pragma unroll
            for (int j = 0; j < 4; j++) Ps[ty * 4 + i][tx * 4 + j] = s[i][j];
        __syncthreads();

#pragma unroll 16
        for (int j = 0; j < 64; j++) {
            float p[4], vv[4];
#pragma unroll
            for (int i = 0; i < 4; i++) p[i] = Ps[ty * 4 + i][j];
#pragma unroll
            for (int b = 0; b < 4; b++) vv[b] = Vs[j][tx * 4 + b];
#pragma unroll
            for (int i = 0; i < 4; i++)
#pragma unroll
                for (int b = 0; b < 4; b++)
                    o[i][b] = fmaf(p[i], vv[b], o[i][b]);
        }
    }

    // normalize and write ctx
#pragma unroll
    for (int i = 0; i < 4; i++) {
        const int r = ty * 4 + i;
        if (r < qrows) {
            const float inv = 1.f / l_i[i];
            float* cp = &g_ctx[(size_t)(q0 + r) * NSTATE + h * HDIM + tx * 4];
#pragma unroll
            for (int j = 0; j < 4; j++) cp[j] = o[i][j] * inv;
        }
    }
}

// ---------------------------------------------------------------------------
// Launch. Inputs: 0=x, 1=cu_seqlens, 2=Wq, 3=bq, 4=Wk, 5=Wv, 6=bv, 7=Wo, 8=bo
// ---------------------------------------------------------------------------
extern "C" void kernel_launch(void* const* d_in, const int* in_sizes, int n_in,
                              void* d_out, int out_size)
{
    const float* x  = (const float*)d_in[0];
    const int*   cu = (const int*)d_in[1];
    const float* Wq = (const float*)d_in[2];
    const float* bq = (const float*)d_in[3];
    const float* Wk = (const float*)d_in[4];
    const float* Wv = (const float*)d_in[5];
    const float* bv = (const float*)d_in[6];
    const float* Wo = (const float*)d_in[7];
    const float* bo = (const float*)d_in[8];

    const int T = in_sizes[0] / NSTATE;       // 6144
    const int nseq = in_sizes[1] - 1;         // 8

    const int attn_smem = 4 * 64 * 65 * (int)sizeof(float);  // 66560 B
    cudaFuncSetAttribute(attn_kernel,
                         cudaFuncAttributeMaxDynamicSharedMemorySize, attn_smem);

    dim3 gqkv(NSTATE / 128, T / 128, 3);
    qkv_kernel<<<gqkv, 256>>>(x, Wq, bq, Wk, Wv, bv, T);

    const int maxTiles = T / 64 + nseq;       // upper bound on sum(ceil(L/64))
    dim3 gattn(maxTiles, NHEAD);
    attn_kernel<<<gattn, 256, attn_smem>>>(cu, nseq);

    dim3 go(NSTATE / 128, T / 128);
    oproj_kernel<<<go, 256>>>(Wo, bo, (float*)d_out, T);
}

// round 3
// speedup vs baseline: 1.6112x; 1.6112x over previous
#include <cuda_runtime.h>
#include <cstdint>

#define NSTATE 1024
#define NHEAD  16
#define HDIM   64
#define TMAX   6144

// Scratch (device globals: allocation-free rule)
__device__ float g_q[TMAX * NSTATE];
__device__ float g_k[TMAX * NSTATE];
__device__ float g_v[TMAX * NSTATE];
__device__ float g_ctx[TMAX * NSTATE];
__device__ float g_xt[TMAX * NSTATE];          // tf32-rounded x
__device__ float g_wqt[NSTATE * NSTATE];       // tf32-rounded weights
__device__ float g_wkt[NSTATE * NSTATE];
__device__ float g_wvt[NSTATE * NSTATE];
__device__ float g_wot[NSTATE * NSTATE];

__device__ __forceinline__ unsigned f2tf(float f) {
    unsigned u; asm("cvt.rna.tf32.f32 %0, %1;" : "=r"(u) : "f"(f)); return u;
}

// ---------------------------------------------------------------------------
// Elementwise tf32-round (round-to-nearest; avoids HMMA truncation bias)
// ---------------------------------------------------------------------------
__global__ __launch_bounds__(256)
void cvt_kernel(const float* __restrict__ s, float* __restrict__ d, int n)
{
    int i = (blockIdx.x * blockDim.x + threadIdx.x) * 4;
    if (i < n) {
        float4 v = *(const float4*)(s + i);
        v.x = __uint_as_float(f2tf(v.x));
        v.y = __uint_as_float(f2tf(v.y));
        v.z = __uint_as_float(f2tf(v.z));
        v.w = __uint_as_float(f2tf(v.w));
        *(float4*)(d + i) = v;
    }
}

// ---------------------------------------------------------------------------
// tf32 tensor-core GEMM NT: C[M,N] = A[M,K] @ W[N,K]^T (+bias)
// CTA 128x128x32, 8 warps (2x4), warp tile 64x32, mma m16n8k8.
// A,W must already be tf32-rounded fp32. cp.async double-buffered.
// ---------------------------------------------------------------------------
#define GSTR 36                 // 32 + 4 pad (floats) -> conflict-free frags
#define GBUF (128 * GSTR)       // floats per matrix per buffer

__device__ __forceinline__ void gemm_tf32_body(const float* __restrict__ A,
                                               const float* __restrict__ W,
                                               const float* __restrict__ bias,
                                               float* __restrict__ C,
                                               int M, int N, int K)
{
    extern __shared__ float sm[];   // [buf0: As,Bs][buf1: As,Bs] = 4*GBUF floats

    const int tid  = threadIdx.x;
    const int lane = tid & 31;
    const int warp = tid >> 5;
    const int wm = (warp >> 2) * 64;     // warp row offset within CTA tile
    const int wn = (warp & 3) * 32;      // warp col offset
    const int bm = blockIdx.y * 128;
    const int bn = blockIdx.x * 128;

    // gmem->smem mapping: row = tid>>1 (0..127), 16-float half = (tid&1)*16
    const int lrow = tid >> 1;
    const int kc0  = (tid & 1) * 16;

    const float* Ag = A + (size_t)(bm + lrow) * K + kc0;
    const float* Wg = W + (size_t)(bn + lrow) * K + kc0;
    const uint32_t sbase = (uint32_t)__cvta_generic_to_shared(sm);
    const uint32_t sA = sbase + (uint32_t)(lrow * GSTR + kc0) * 4u;
    const uint32_t sB = sA + (uint32_t)GBUF * 4u;

    float acc[4][4][4];
#pragma unroll
    for (int a = 0; a < 4; a++)
#pragma unroll
        for (int b = 0; b < 4; b++)
#pragma unroll
            for (int c = 0; c < 4; c++) acc[a][b][c] = 0.f;

    const int T = K / 32;

    // prologue: issue tile 0 into buffer 0
#pragma unroll
    for (int j = 0; j < 4; j++) {
        asm volatile("cp.async.ca.shared.global [%0], [%1], 16;\n"
                     :: "r"(sA + j * 16), "l"(Ag + j * 4));
        asm volatile("cp.async.ca.shared.global [%0], [%1], 16;\n"
                     :: "r"(sB + j * 16), "l"(Wg + j * 4));
    }
    asm volatile("cp.async.commit_group;\n");

    for (int t = 0; t < T; t++) {
        if (t + 1 < T) {
            const uint32_t off = (uint32_t)((t + 1) & 1) * (2u * GBUF * 4u);
            const float* ag = Ag + (t + 1) * 32;
            const float* wg = Wg + (t + 1) * 32;
#pragma unroll
            for (int j = 0; j < 4; j++) {
                asm volatile("cp.async.ca.shared.global [%0], [%1], 16;\n"
                             :: "r"(sA + off + j * 16), "l"(ag + j * 4));
                asm volatile("cp.async.ca.shared.global [%0], [%1], 16;\n"
                             :: "r"(sB + off + j * 16), "l"(wg + j * 4));
            }
            asm volatile("cp.async.commit_group;\n");
            asm volatile("cp.async.wait_group 1;\n");
        } else {
            asm volatile("cp.async.wait_group 0;\n");
        }
        __syncthreads();

        const float* As = sm + (t & 1) * 2 * GBUF;
        const float* Bs = As + GBUF;

#pragma unroll
        for (int ks = 0; ks < 4; ks++) {
            const int k = ks * 8 + (lane & 3);
            unsigned af[4][4], bf[4][2];
#pragma unroll
            for (int mt = 0; mt < 4; mt++) {
                const int r = wm + mt * 16 + (lane >> 2);
                af[mt][0] = __float_as_uint(As[r * GSTR + k]);
                af[mt][1] = __float_as_uint(As[(r + 8) * GSTR + k]);
                af[mt][2] = __float_as_uint(As[r * GSTR + k + 4]);
                af[mt][3] = __float_as_uint(As[(r + 8) * GSTR + k + 4]);
            }
#pragma unroll
            for (int nt = 0; nt < 4; nt++) {
                const int c = wn + nt * 8 + (lane >> 2);
                bf[nt][0] = __float_as_uint(Bs[c * GSTR + k]);
                bf[nt][1] = __float_as_uint(Bs[c * GSTR + k + 4]);
            }
#pragma unroll
            for (int mt = 0; mt < 4; mt++)
#pragma unroll
                for (int nt = 0; nt < 4; nt++)
                    asm volatile(
                        "mma.sync.aligned.m16n8k8.row.col.f32.tf32.tf32.f32 "
                        "{%0,%1,%2,%3}, {%4,%5,%6,%7}, {%8,%9}, {%0,%1,%2,%3};\n"
                        : "+f"(acc[mt][nt][0]), "+f"(acc[mt][nt][1]),
                          "+f"(acc[mt][nt][2]), "+f"(acc[mt][nt][3])
                        : "r"(af[mt][0]), "r"(af[mt][1]),
                          "r"(af[mt][2]), "r"(af[mt][3]),
                          "r"(bf[nt][0]), "r"(bf[nt][1]));
        }
        __syncthreads();
    }

    // epilogue: c0,c1 at (row, 2t), (row, 2t+1); c2,c3 at row+8
#pragma unroll
    for (int nt = 0; nt < 4; nt++) {
        const int c = bn + wn + nt * 8 + (lane & 3) * 2;
        const float b0 = bias ? bias[c] : 0.f;
        const float b1 = bias ? bias[c + 1] : 0.f;
#pragma unroll
        for (int mt = 0; mt < 4; mt++) {
            const int r = bm + wm + mt * 16 + (lane >> 2);
            float2 v0 = make_float2(acc[mt][nt][0] + b0, acc[mt][nt][1] + b1);
            float2 v1 = make_float2(acc[mt][nt][2] + b0, acc[mt][nt][3] + b1);
            *(float2*)(C + (size_t)r * NSTATE + c)       = v0;
            *(float2*)(C + (size_t)(r + 8) * NSTATE + c) = v1;
        }
    }
}

__global__ __launch_bounds__(256)
void qkv_tf32_kernel(const float* __restrict__ bq, const float* __restrict__ bv, int M)
{
    if (blockIdx.z == 0)      gemm_tf32_body(g_xt, g_wqt, bq,      g_q, M, NSTATE, NSTATE);
    else if (blockIdx.z == 1) gemm_tf32_body(g_xt, g_wkt, nullptr, g_k, M, NSTATE, NSTATE);
    else                      gemm_tf32_body(g_xt, g_wvt, bv,      g_v, M, NSTATE, NSTATE);
}

__global__ __launch_bounds__(256)
void oproj_tf32_kernel(const float* __restrict__ bo, float* __restrict__ out, int M)
{
    // g_ctx already tf32-rounded by attention epilogue
    gemm_tf32_body(g_ctx, g_wot, bo, out, M, NSTATE, NSTATE);
}

// ---------------------------------------------------------------------------
// Flash attention (fp32): one CTA per (64-query tile, head). Online softmax.
// ---------------------------------------------------------------------------
__global__ __launch_bounds__(256)
void attn_kernel(const int* __restrict__ cu, int nseq)
{
    extern __shared__ float smf[];
    float (*Qs)[65] = (float(*)[65])(smf);
    float (*Ks)[65] = (float(*)[65])(smf + 64 * 65);
    float (*Vs)[65] = (float(*)[65])(smf + 2 * 64 * 65);
    float (*Ps)[65] = (float(*)[65])(smf + 3 * 64 * 65);

    const int h = blockIdx.y;

    int s0 = 0, L = 0, q0 = 0, found = 0;
    {
        int acct = 0;
        const int gt = blockIdx.x;
        for (int b = 0; b < nseq; b++) {
            const int s = cu[b], e = cu[b + 1];
            const int Lb = e - s;
            const int nt = (Lb + 63) >> 6;
            if (gt < acct + nt) { s0 = s; L = Lb; q0 = s + (gt - acct) * 64; found = 1; break; }
            acct += nt;
        }
    }
    if (!found) return;

    const int tid = threadIdx.x;
    const int tx = tid & 15, ty = tid >> 4;
    const int qrows = min(64, s0 + L - q0);

#pragma unroll
    for (int it = 0; it < 16; it++) {
        const int idx = tid + it * 256;
        const int r = idx >> 6, c = idx & 63;
        Qs[r][c] = (r < qrows) ? g_q[(size_t)(q0 + r) * NSTATE + h * HDIM + c] * 0.125f : 0.f;
    }

    float m_i[4], l_i[4], o[4][4];
#pragma unroll
    for (int i = 0; i < 4; i++) {
        m_i[i] = -1e30f; l_i[i] = 0.f;
#pragma unroll
        for (int j = 0; j < 4; j++) o[i][j] = 0.f;
    }

    const int nkt = (L + 63) >> 6;
    for (int kt = 0; kt < nkt; kt++) {
        const int kbase = kt * 64;
        const int kc = min(64, L - kbase);

        __syncthreads();
#pragma unroll
        for (int it = 0; it < 16; it++) {
            const int idx = tid + it * 256;
            const int r = idx >> 6, c = idx & 63;
            const bool ok = (r < kc);
            const size_t g = (size_t)(s0 + kbase + r) * NSTATE + h * HDIM + c;
            Ks[r][c] = ok ? g_k[g] : 0.f;
            Vs[r][c] = ok ? g_v[g] : 0.f;
        }
        __syncthreads();

        float s[4][4];
#pragma unroll
        for (int i = 0; i < 4; i++)
#pragma unroll
            for (int j = 0; j < 4; j++) s[i][j] = 0.f;

#pragma unroll 16
        for (int d = 0; d < 64; d++) {
            float a[4], b[4];
#pragma unroll
            for (int i = 0; i < 4; i++) a[i] = Qs[ty * 4 + i][d];
#pragma unroll
            for (int j = 0; j < 4; j++) b[j] = Ks[tx * 4 + j][d];
#pragma unroll
            for (int i = 0; i < 4; i++)
#pragma unroll
                for (int j = 0; j < 4; j++)
                    s[i][j] = fmaf(a[i], b[j], s[i][j]);
        }

        if (kc < 64) {
#pragma unroll
            for (int j = 0; j < 4; j++)
                if (tx * 4 + j >= kc) {
#pragma unroll
                    for (int i = 0; i < 4; i++) s[i][j] = -1e30f;
                }
        }

#pragma unroll
        for (int i = 0; i < 4; i++) {
            float mt = fmaxf(fmaxf(s[i][0], s[i][1]), fmaxf(s[i][2], s[i][3]));
#pragma unroll
            for (int msk = 1; msk < 16; msk <<= 1)
                mt = fmaxf(mt, __shfl_xor_sync(0xffffffffu, mt, msk));
            const float mn = fmaxf(m_i[i], mt);
            const float alpha = __expf(m_i[i] - mn);
            float r = 0.f;
#pragma unroll
            for (int j = 0; j < 4; j++) { s[i][j] = __expf(s[i][j] - mn); r += s[i][j]; }
#pragma unroll
            for (int msk = 1; msk < 16; msk <<= 1)
                r += __shfl_xor_sync(0xffffffffu, r, msk);
            l_i[i] = l_i[i] * alpha + r;
            m_i[i] = mn;
#pragma unroll
            for (int j = 0; j < 4; j++) o[i][j] *= alpha;
        }

#pragma unroll
        for (int i = 0; i < 4; i++)
#pragma unroll
            for (int j = 0; j < 4; j++) Ps[ty * 4 + i][tx * 4 + j] = s[i][j];
        __syncthreads();

#pragma unroll 16
        for (int j = 0; j < 64; j++) {
            float p[4], vv[4];
#pragma unroll
            for (int i = 0; i < 4; i++) p[i] = Ps[ty * 4 + i][j];
#pragma unroll
            for (int b = 0; b < 4; b++) vv[b] = Vs[j][tx * 4 + b];
#pragma unroll
            for (int i = 0; i < 4; i++)
#pragma unroll
                for (int b = 0; b < 4; b++)
                    o[i][b] = fmaf(p[i], vv[b], o[i][b]);
        }
    }

    // normalize and write ctx — tf32-rounded so oproj needs no extra pass
#pragma unroll
    for (int i = 0; i < 4; i++) {
        const int r = ty * 4 + i;
        if (r < qrows) {
            const float inv = 1.f / l_i[i];
            float* cp = &g_ctx[(size_t)(q0 + r) * NSTATE + h * HDIM + tx * 4];
#pragma unroll
            for (int j = 0; j < 4; j++)
                cp[j] = __uint_as_float(f2tf(o[i][j] * inv));
        }
    }
}

// ---------------------------------------------------------------------------
// Launch. Inputs: 0=x, 1=cu_seqlens, 2=Wq, 3=bq, 4=Wk, 5=Wv, 6=bv, 7=Wo, 8=bo
// ---------------------------------------------------------------------------
extern "C" void kernel_launch(void* const* d_in, const int* in_sizes, int n_in,
                              void* d_out, int out_size)
{
    const float* x  = (const float*)d_in[0];
    const int*   cu = (const int*)d_in[1];
    const float* bq = (const float*)d_in[3];
    const float* Wq = (const float*)d_in[2];
    const float* Wk = (const float*)d_in[4];
    const float* Wv = (const float*)d_in[5];
    const float* bv = (const float*)d_in[6];
    const float* Wo = (const float*)d_in[7];
    const float* bo = (const float*)d_in[8];

    const int T = in_sizes[0] / NSTATE;       // 6144
    const int nseq = in_sizes[1] - 1;         // 8

    const int gemm_smem = 4 * GBUF * (int)sizeof(float);      // 73728 B
    const int attn_smem = 4 * 64 * 65 * (int)sizeof(float);   // 66560 B
    cudaFuncSetAttribute(qkv_tf32_kernel,
                         cudaFuncAttributeMaxDynamicSharedMemorySize, gemm_smem);
    cudaFuncSetAttribute(oproj_tf32_kernel,
                         cudaFuncAttributeMaxDynamicSharedMemorySize, gemm_smem);
    cudaFuncSetAttribute(attn_kernel,
                         cudaFuncAttributeMaxDynamicSharedMemorySize, attn_smem);

    // tf32-round inputs and weights
    float* xt;  cudaGetSymbolAddress((void**)&xt,  g_xt);
    float* wqt; cudaGetSymbolAddress((void**)&wqt, g_wqt);
    float* wkt; cudaGetSymbolAddress((void**)&wkt, g_wkt);
    float* wvt; cudaGetSymbolAddress((void**)&wvt, g_wvt);
    float* wot; cudaGetSymbolAddress((void**)&wot, g_wot);

    const int nX = T * NSTATE, nW = NSTATE * NSTATE;
    cvt_kernel<<<(nX / 4 + 255) / 256, 256>>>(x,  xt,  nX);
    cvt_kernel<<<(nW / 4 + 255) / 256, 256>>>(Wq, wqt, nW);
    cvt_kernel<<<(nW / 4 + 255) / 256, 256>>>(Wk, wkt, nW);
    cvt_kernel<<<(nW / 4 + 255) / 256, 256>>>(Wv, wvt, nW);
    cvt_kernel<<<(nW / 4 + 255) / 256, 256>>>(Wo, wot, nW);

    dim3 gqkv(NSTATE / 128, T / 128, 3);
    qkv_tf32_kernel<<<gqkv, 256, gemm_smem>>>(bq, bv, T);

    const int maxTiles = T / 64 + nseq;
    dim3 gattn(maxTiles, NHEAD);
    attn_kernel<<<gattn, 256, attn_smem>>>(cu, nseq);

    dim3 go(NSTATE / 128, T / 128);
    oproj_tf32_kernel<<<go, 256, gemm_smem>>>(bo, (float*)d_out, T);
}

// round 4
// speedup vs baseline: 2.6931x; 1.6714x over previous
#include <cuda_runtime.h>
#include <cstdint>

#define NSTATE 1024
#define NHEAD  16
#define HDIM   64
#define TMAX   6144

// Scratch (device globals: allocation-free rule)
__device__ float g_q[TMAX * NSTATE];
__device__ float g_k[TMAX * NSTATE];
__device__ float g_v[TMAX * NSTATE];
__device__ float g_ctx[TMAX * NSTATE];
__device__ float g_xt[TMAX * NSTATE];          // tf32-rounded x
__device__ float g_wqt[NSTATE * NSTATE];       // tf32-rounded weights
__device__ float g_wkt[NSTATE * NSTATE];
__device__ float g_wvt[NSTATE * NSTATE];
__device__ float g_wot[NSTATE * NSTATE];

__device__ __forceinline__ unsigned f2tf(float f) {
    unsigned u; asm("cvt.rna.tf32.f32 %0, %1;" : "=r"(u) : "f"(f)); return u;
}
__device__ __forceinline__ float tfr(float f) { return __uint_as_float(f2tf(f)); }

// FMA-only exp2 for y <= 0 (softmax path). |rel err| ~ 2e-6.
__device__ __forceinline__ float exp2f_fast(float y) {
    y = fmaxf(y, -100.f);
    float z = __fadd_rn(y, 12582912.f);      // 1.5*2^23 magic
    float r = __fsub_rn(z, 12582912.f);      // round-to-nearest-int(y)
    float f = y - r;                         // [-0.5, 0.5]
    int   n = __float_as_int(z) - 0x4B400000;
    float p = 1.3333558e-3f;
    p = fmaf(p, f, 9.6181291e-3f);
    p = fmaf(p, f, 5.5504109e-2f);
    p = fmaf(p, f, 2.4022651e-1f);
    p = fmaf(p, f, 6.9314718e-1f);
    p = fmaf(p, f, 1.0f);
    return __int_as_float(__float_as_int(p) + (n << 23));
}

// ---------------------------------------------------------------------------
// Elementwise tf32-round
// ---------------------------------------------------------------------------
__global__ __launch_bounds__(256)
void cvt_kernel(const float* __restrict__ s, float* __restrict__ d, int n)
{
    int i = (blockIdx.x * blockDim.x + threadIdx.x) * 4;
    if (i < n) {
        float4 v = *(const float4*)(s + i);
        v.x = tfr(v.x); v.y = tfr(v.y); v.z = tfr(v.z); v.w = tfr(v.w);
        *(float4*)(d + i) = v;
    }
}

// ---------------------------------------------------------------------------
// tf32 tensor-core GEMM NT: C[M,N] = A[M,K] @ W[N,K]^T (+bias)
// Optional tf32-rounding of the output (for K/V feeding attention MMA).
// ---------------------------------------------------------------------------
#define GSTR 36
#define GBUF (128 * GSTR)

__device__ __forceinline__ void gemm_tf32_body(const float* __restrict__ A,
                                               const float* __restrict__ W,
                                               const float* __restrict__ bias,
                                               float* __restrict__ C,
                                               int M, int N, int K, bool rnd)
{
    extern __shared__ float sm[];

    const int tid  = threadIdx.x;
    const int lane = tid & 31;
    const int warp = tid >> 5;
    const int wm = (warp >> 2) * 64;
    const int wn = (warp & 3) * 32;
    const int bm = blockIdx.y * 128;
    const int bn = blockIdx.x * 128;

    const int lrow = tid >> 1;
    const int kc0  = (tid & 1) * 16;

    const float* Ag = A + (size_t)(bm + lrow) * K + kc0;
    const float* Wg = W + (size_t)(bn + lrow) * K + kc0;
    const uint32_t sbase = (uint32_t)__cvta_generic_to_shared(sm);
    const uint32_t sA = sbase + (uint32_t)(lrow * GSTR + kc0) * 4u;
    const uint32_t sB = sA + (uint32_t)GBUF * 4u;

    float acc[4][4][4];
#pragma unroll
    for (int a = 0; a < 4; a++)
#pragma unroll
        for (int b = 0; b < 4; b++)
#pragma unroll
            for (int c = 0; c < 4; c++) acc[a][b][c] = 0.f;

    const int T = K / 32;

#pragma unroll
    for (int j = 0; j < 4; j++) {
        asm volatile("cp.async.ca.shared.global [%0], [%1], 16;\n"
                     :: "r"(sA + j * 16), "l"(Ag + j * 4));
        asm volatile("cp.async.ca.shared.global [%0], [%1], 16;\n"
                     :: "r"(sB + j * 16), "l"(Wg + j * 4));
    }
    asm volatile("cp.async.commit_group;\n");

    for (int t = 0; t < T; t++) {
        if (t + 1 < T) {
            const uint32_t off = (uint32_t)((t + 1) & 1) * (2u * GBUF * 4u);
            const float* ag = Ag + (t + 1) * 32;
            const float* wg = Wg + (t + 1) * 32;
#pragma unroll
            for (int j = 0; j < 4; j++) {
                asm volatile("cp.async.ca.shared.global [%0], [%1], 16;\n"
                             :: "r"(sA + off + j * 16), "l"(ag + j * 4));
                asm volatile("cp.async.ca.shared.global [%0], [%1], 16;\n"
                             :: "r"(sB + off + j * 16), "l"(wg + j * 4));
            }
            asm volatile("cp.async.commit_group;\n");
            asm volatile("cp.async.wait_group 1;\n");
        } else {
            asm volatile("cp.async.wait_group 0;\n");
        }
        __syncthreads();

        const float* As = sm + (t & 1) * 2 * GBUF;
        const float* Bs = As + GBUF;

#pragma unroll
        for (int ks = 0; ks < 4; ks++) {
            const int k = ks * 8 + (lane & 3);
            unsigned af[4][4], bf[4][2];
#pragma unroll
            for (int mt = 0; mt < 4; mt++) {
                const int r = wm + mt * 16 + (lane >> 2);
                af[mt][0] = __float_as_uint(As[r * GSTR + k]);
                af[mt][1] = __float_as_uint(As[(r + 8) * GSTR + k]);
                af[mt][2] = __float_as_uint(As[r * GSTR + k + 4]);
                af[mt][3] = __float_as_uint(As[(r + 8) * GSTR + k + 4]);
            }
#pragma unroll
            for (int nt = 0; nt < 4; nt++) {
                const int c = wn + nt * 8 + (lane >> 2);
                bf[nt][0] = __float_as_uint(Bs[c * GSTR + k]);
                bf[nt][1] = __float_as_uint(Bs[c * GSTR + k + 4]);
            }
#pragma unroll
            for (int mt = 0; mt < 4; mt++)
#pragma unroll
                for (int nt = 0; nt < 4; nt++)
                    asm volatile(
                        "mma.sync.aligned.m16n8k8.row.col.f32.tf32.tf32.f32 "
                        "{%0,%1,%2,%3}, {%4,%5,%6,%7}, {%8,%9}, {%0,%1,%2,%3};\n"
                        : "+f"(acc[mt][nt][0]), "+f"(acc[mt][nt][1]),
                          "+f"(acc[mt][nt][2]), "+f"(acc[mt][nt][3])
                        : "r"(af[mt][0]), "r"(af[mt][1]),
                          "r"(af[mt][2]), "r"(af[mt][3]),
                          "r"(bf[nt][0]), "r"(bf[nt][1]));
        }
        __syncthreads();
    }

#pragma unroll
    for (int nt = 0; nt < 4; nt++) {
        const int c = bn + wn + nt * 8 + (lane & 3) * 2;
        const float b0 = bias ? bias[c] : 0.f;
        const float b1 = bias ? bias[c + 1] : 0.f;
#pragma unroll
        for (int mt = 0; mt < 4; mt++) {
            const int r = bm + wm + mt * 16 + (lane >> 2);
            float2 v0 = make_float2(acc[mt][nt][0] + b0, acc[mt][nt][1] + b1);
            float2 v1 = make_float2(acc[mt][nt][2] + b0, acc[mt][nt][3] + b1);
            if (rnd) {
                v0.x = tfr(v0.x); v0.y = tfr(v0.y);
                v1.x = tfr(v1.x); v1.y = tfr(v1.y);
            }
            *(float2*)(C + (size_t)r * NSTATE + c)       = v0;
            *(float2*)(C + (size_t)(r + 8) * NSTATE + c) = v1;
        }
    }
}

__global__ __launch_bounds__(256)
void qkv_tf32_kernel(const float* __restrict__ bq, const float* __restrict__ bv, int M)
{
    if (blockIdx.z == 0)      gemm_tf32_body(g_xt, g_wqt, bq,      g_q, M, NSTATE, NSTATE, false);
    else if (blockIdx.z == 1) gemm_tf32_body(g_xt, g_wkt, nullptr, g_k, M, NSTATE, NSTATE, true);
    else                      gemm_tf32_body(g_xt, g_wvt, bv,      g_v, M, NSTATE, NSTATE, true);
}

__global__ __launch_bounds__(256)
void oproj_tf32_kernel(const float* __restrict__ bo, float* __restrict__ out, int M)
{
    gemm_tf32_body(g_ctx, g_wot, bo, out, M, NSTATE, NSTATE, false);
}

// ---------------------------------------------------------------------------
// Flash attention, tf32 mma.sync + FMA-only exp2 softmax (log2 domain).
// CTA: 64 queries x 1 head, 4 warps x 16 query rows. Key tiles of 64.
// smem: QPs (Q tile, reused for P) stride 68; Ks stride 68; Vs stride 72.
// ---------------------------------------------------------------------------
#define AS 68
#define VS 72
#define QSCALE (0.125f * 1.44269504088896340736f)   // 1/sqrt(64) * log2(e)

__global__ __launch_bounds__(128)
void attn_mma_kernel(const int* __restrict__ cu, int nseq)
{
    extern __shared__ float smf[];
    float* QPs = smf;               // 64*AS
    float* Ks  = smf + 64 * AS;     // 64*AS
    float* Vs  = Ks  + 64 * AS;     // 64*VS

    const int h = blockIdx.y;

    int s0 = 0, L = 0, q0 = 0, found = 0;
    {
        int acct = 0;
        const int gt = blockIdx.x;
        for (int b = 0; b < nseq; b++) {
            const int s = cu[b], e = cu[b + 1];
            const int Lb = e - s;
            const int nt = (Lb + 63) >> 6;
            if (gt < acct + nt) { s0 = s; L = Lb; q0 = s + (gt - acct) * 64; found = 1; break; }
            acct += nt;
        }
    }
    if (!found) return;

    const int tid = threadIdx.x, lane = tid & 31, warp = tid >> 5;
    const int g = lane >> 2, tg = lane & 3;
    const int qrow0 = warp * 16;
    const int qrows = min(64, s0 + L - q0);

    // Q fill: scaled + tf32-rounded
#pragma unroll
    for (int it = 0; it < 8; it++) {
        const int idx = tid + it * 128;
        const int r = idx >> 4, c4 = (idx & 15) * 4;
        float4 v = make_float4(0.f, 0.f, 0.f, 0.f);
        if (r < qrows)
            v = *(const float4*)&g_q[(size_t)(q0 + r) * NSTATE + h * HDIM + c4];
        v.x = tfr(v.x * QSCALE); v.y = tfr(v.y * QSCALE);
        v.z = tfr(v.z * QSCALE); v.w = tfr(v.w * QSCALE);
        *(float4*)&QPs[r * AS + c4] = v;
    }
    __syncthreads();

    // Q fragments register-resident (warp reads only its own 16 rows)
    unsigned qf[8][4];
#pragma unroll
    for (int ks = 0; ks < 8; ks++) {
        const float* qb = &QPs[(qrow0 + g) * AS + ks * 8 + tg];
        qf[ks][0] = __float_as_uint(qb[0]);
        qf[ks][1] = __float_as_uint(qb[8 * AS]);
        qf[ks][2] = __float_as_uint(qb[4]);
        qf[ks][3] = __float_as_uint(qb[8 * AS + 4]);
    }

    float m0 = -1e30f, m1 = -1e30f, l0 = 0.f, l1 = 0.f;
    float o[8][4];
#pragma unroll
    for (int nt = 0; nt < 8; nt++)
#pragma unroll
        for (int j = 0; j < 4; j++) o[nt][j] = 0.f;

    const int nkt = (L + 63) >> 6;
    for (int kt = 0; kt < nkt; kt++) {
        const int kbase = kt * 64;
        const int kc = min(64, L - kbase);

        __syncthreads();   // protect prev Ks/Vs reads
#pragma unroll
        for (int it = 0; it < 8; it++) {
            const int idx = tid + it * 128;
            const int r = idx >> 4, c4 = (idx & 15) * 4;
            float4 kv = make_float4(0.f, 0.f, 0.f, 0.f);
            float4 vv = make_float4(0.f, 0.f, 0.f, 0.f);
            if (r < kc) {
                const size_t go = (size_t)(s0 + kbase + r) * NSTATE + h * HDIM + c4;
                kv = *(const float4*)&g_k[go];
                vv = *(const float4*)&g_v[go];
            }
            *(float4*)&Ks[r * AS + c4] = kv;
            *(float4*)&Vs[r * VS + c4] = vv;
        }
        __syncthreads();

        // S = Q @ K^T  (log2 domain; scale folded into Q)
        float s[8][4];
#pragma unroll
        for (int nt = 0; nt < 8; nt++)
#pragma unroll
            for (int j = 0; j < 4; j++) s[nt][j] = 0.f;

#pragma unroll
        for (int ks = 0; ks < 8; ks++) {
#pragma unroll
            for (int nt = 0; nt < 8; nt++) {
                const float* kb = &Ks[(nt * 8 + g) * AS + ks * 8 + tg];
                const unsigned b0 = __float_as_uint(kb[0]);
                const unsigned b1 = __float_as_uint(kb[4]);
                asm volatile(
                    "mma.sync.aligned.m16n8k8.row.col.f32.tf32.tf32.f32 "
                    "{%0,%1,%2,%3}, {%4,%5,%6,%7}, {%8,%9}, {%0,%1,%2,%3};\n"
                    : "+f"(s[nt][0]), "+f"(s[nt][1]), "+f"(s[nt][2]), "+f"(s[nt][3])
                    : "r"(qf[ks][0]), "r"(qf[ks][1]), "r"(qf[ks][2]), "r"(qf[ks][3]),
                      "r"(b0), "r"(b1));
            }
        }

        if (kc < 64) {
#pragma unroll
            for (int nt = 0; nt < 8; nt++) {
                const int c = nt * 8 + 2 * tg;
                if (c >= kc)     { s[nt][0] = -1e30f; s[nt][2] = -1e30f; }
                if (c + 1 >= kc) { s[nt][1] = -1e30f; s[nt][3] = -1e30f; }
            }
        }

        // online softmax, log2 domain, FMA-only exp2
        float mt0 = -1e30f, mt1 = -1e30f;
#pragma unroll
        for (int nt = 0; nt < 8; nt++) {
            mt0 = fmaxf(mt0, fmaxf(s[nt][0], s[nt][1]));
            mt1 = fmaxf(mt1, fmaxf(s[nt][2], s[nt][3]));
        }
        mt0 = fmaxf(mt0, __shfl_xor_sync(0xffffffffu, mt0, 1));
        mt0 = fmaxf(mt0, __shfl_xor_sync(0xffffffffu, mt0, 2));
        mt1 = fmaxf(mt1, __shfl_xor_sync(0xffffffffu, mt1, 1));
        mt1 = fmaxf(mt1, __shfl_xor_sync(0xffffffffu, mt1, 2));

        const float mn0 = fmaxf(m0, mt0), mn1 = fmaxf(m1, mt1);
        const float a0 = exp2f_fast(m0 - mn0), a1 = exp2f_fast(m1 - mn1);
        float r0 = 0.f, r1 = 0.f;
#pragma unroll
        for (int nt = 0; nt < 8; nt++) {
            s[nt][0] = tfr(exp2f_fast(s[nt][0] - mn0)); r0 += s[nt][0];
            s[nt][1] = tfr(exp2f_fast(s[nt][1] - mn0)); r0 += s[nt][1];
            s[nt][2] = tfr(exp2f_fast(s[nt][2] - mn1)); r1 += s[nt][2];
            s[nt][3] = tfr(exp2f_fast(s[nt][3] - mn1)); r1 += s[nt][3];
        }
        r0 += __shfl_xor_sync(0xffffffffu, r0, 1);
        r0 += __shfl_xor_sync(0xffffffffu, r0, 2);
        r1 += __shfl_xor_sync(0xffffffffu, r1, 1);
        r1 += __shfl_xor_sync(0xffffffffu, r1, 2);
        l0 = l0 * a0 + r0; l1 = l1 * a1 + r1;
        m0 = mn0; m1 = mn1;
#pragma unroll
        for (int nt = 0; nt < 8; nt++) {
            o[nt][0] *= a0; o[nt][1] *= a0;
            o[nt][2] *= a1; o[nt][3] *= a1;
        }

        // P -> smem (C-layout store, A-layout reload; per-warp private rows)
#pragma unroll
        for (int nt = 0; nt < 8; nt++) {
            float* pb = &QPs[(qrow0 + g) * AS + nt * 8 + 2 * tg];
            *(float2*)pb            = make_float2(s[nt][0], s[nt][1]);
            *(float2*)(pb + 8 * AS) = make_float2(s[nt][2], s[nt][3]);
        }
        __syncwarp();

        // O += P @ V
#pragma unroll
        for (int ks = 0; ks < 8; ks++) {
            const float* pb = &QPs[(qrow0 + g) * AS + ks * 8 + tg];
            const unsigned pa0 = __float_as_uint(pb[0]);
            const unsigned pa1 = __float_as_uint(pb[8 * AS]);
            const unsigned pa2 = __float_as_uint(pb[4]);
            const unsigned pa3 = __float_as_uint(pb[8 * AS + 4]);
#pragma unroll
            for (int nt = 0; nt < 8; nt++) {
                const float* vb = &Vs[(ks * 8 + tg) * VS + nt * 8 + g];
                const unsigned b0 = __float_as_uint(vb[0]);
                const unsigned b1 = __float_as_uint(vb[4 * VS]);
                asm volatile(
                    "mma.sync.aligned.m16n8k8.row.col.f32.tf32.tf32.f32 "
                    "{%0,%1,%2,%3}, {%4,%5,%6,%7}, {%8,%9}, {%0,%1,%2,%3};\n"
                    : "+f"(o[nt][0]), "+f"(o[nt][1]), "+f"(o[nt][2]), "+f"(o[nt][3])
                    : "r"(pa0), "r"(pa1), "r"(pa2), "r"(pa3),
                      "r"(b0), "r"(b1));
            }
        }
    }

    // normalize + tf32-round + write ctx
    const float il0 = 1.f / l0, il1 = 1.f / l1;
    const int r0g = qrow0 + g, r1g = r0g + 8;
#pragma unroll
    for (int nt = 0; nt < 8; nt++) {
        const int c = nt * 8 + 2 * tg;
        if (r0g < qrows) {
            float2 w = make_float2(tfr(o[nt][0] * il0), tfr(o[nt][1] * il0));
            *(float2*)&g_ctx[(size_t)(q0 + r0g) * NSTATE + h * HDIM + c] = w;
        }
        if (r1g < qrows) {
            float2 w = make_float2(tfr(o[nt][2] * il1), tfr(o[nt][3] * il1));
            *(float2*)&g_ctx[(size_t)(q0 + r1g) * NSTATE + h * HDIM + c] = w;
        }
    }
}

// ---------------------------------------------------------------------------
// Launch. Inputs: 0=x, 1=cu_seqlens, 2=Wq, 3=bq, 4=Wk, 5=Wv, 6=bv, 7=Wo, 8=bo
// ---------------------------------------------------------------------------
extern "C" void kernel_launch(void* const* d_in, const int* in_sizes, int n_in,
                              void* d_out, int out_size)
{
    const float* x  = (const float*)d_in[0];
    const int*   cu = (const int*)d_in[1];
    const float* Wq = (const float*)d_in[2];
    const float* bq = (const float*)d_in[3];
    const float* Wk = (const float*)d_in[4];
    const float* Wv = (const float*)d_in[5];
    const float* bv = (const float*)d_in[6];
    const float* Wo = (const float*)d_in[7];
    const float* bo = (const float*)d_in[8];

    const int T = in_sizes[0] / NSTATE;       // 6144
    const int nseq = in_sizes[1] - 1;         // 8

    const int gemm_smem = 4 * GBUF * (int)sizeof(float);             // 73728 B
    const int attn_smem = (2 * 64 * AS + 64 * VS) * (int)sizeof(float); // 53248 B
    cudaFuncSetAttribute(qkv_tf32_kernel,
                         cudaFuncAttributeMaxDynamicSharedMemorySize, gemm_smem);
    cudaFuncSetAttribute(oproj_tf32_kernel,
                         cudaFuncAttributeMaxDynamicSharedMemorySize, gemm_smem);
    cudaFuncSetAttribute(attn_mma_kernel,
                         cudaFuncAttributeMaxDynamicSharedMemorySize, attn_smem);

    float* xt;  cudaGetSymbolAddress((void**)&xt,  g_xt);
    float* wqt; cudaGetSymbolAddress((void**)&wqt, g_wqt);
    float* wkt; cudaGetSymbolAddress((void**)&wkt, g_wkt);
    float* wvt; cudaGetSymbolAddress((void**)&wvt, g_wvt);
    float* wot; cudaGetSymbolAddress((void**)&wot, g_wot);

    const int nX = T * NSTATE, nW = NSTATE * NSTATE;
    cvt_kernel<<<(nX / 4 + 255) / 256, 256>>>(x,  xt,  nX);
    cvt_kernel<<<(nW / 4 + 255) / 256, 256>>>(Wq, wqt, nW);
    cvt_kernel<<<(nW / 4 + 255) / 256, 256>>>(Wk, wkt, nW);
    cvt_kernel<<<(nW / 4 + 255) / 256, 256>>>(Wv, wvt, nW);
    cvt_kernel<<<(nW / 4 + 255) / 256, 256>>>(Wo, wot, nW);

    dim3 gqkv(NSTATE / 128, T / 128, 3);
    qkv_tf32_kernel<<<gqkv, 256, gemm_smem>>>(bq, bv, T);

    const int maxTiles = T / 64 + nseq;
    dim3 gattn(maxTiles, NHEAD);
    attn_mma_kernel<<<gattn, 128, attn_smem>>>(cu, nseq);

    dim3 go(NSTATE / 128, T / 128);
    oproj_tf32_kernel<<<go, 256, gemm_smem>>>(bo, (float*)d_out, T);
}

// round 6
// speedup vs baseline: 4.7786x; 1.7744x over previous
#include <cuda_runtime.h>
#include <cuda_fp16.h>
#include <cstdint>

#define NSTATE 1024
#define NHEAD  16
#define HDIM   64
#define TMAX   6144

// Scratch (device globals: allocation-free rule). All activations in fp16.
__device__ __half g_qh[TMAX * NSTATE];     // pre-scaled by QSCALE
__device__ __half g_kh[TMAX * NSTATE];
__device__ __half g_vh[TMAX * NSTATE];
__device__ __half g_ctxh[TMAX * NSTATE];
__device__ __half g_xh[TMAX * NSTATE];
__device__ __half g_wqh[NSTATE * NSTATE];
__device__ __half g_wkh[NSTATE * NSTATE];
__device__ __half g_wvh[NSTATE * NSTATE];
__device__ __half g_woh[NSTATE * NSTATE];

#define QSCALE (0.125f * 1.44269504088896340736f)   // 1/sqrt(64) * log2(e)

// FMA-only exp2 for y <= 0 (softmax path). |rel err| ~ 2e-6.
__device__ __forceinline__ float exp2f_fast(float y) {
    y = fmaxf(y, -100.f);
    float z = __fadd_rn(y, 12582912.f);
    float r = __fsub_rn(z, 12582912.f);
    float f = y - r;
    int   n = __float_as_int(z) - 0x4B400000;
    float p = 1.3333558e-3f;
    p = fmaf(p, f, 9.6181291e-3f);
    p = fmaf(p, f, 5.5504109e-2f);
    p = fmaf(p, f, 2.4022651e-1f);
    p = fmaf(p, f, 6.9314718e-1f);
    p = fmaf(p, f, 1.0f);
    return __int_as_float(__float_as_int(p) + (n << 23));
}

__device__ __forceinline__ unsigned h2u(__half2 h) {
    return *reinterpret_cast<unsigned*>(&h);
}

// ---------------------------------------------------------------------------
// Fused fp32 -> fp16 conversion of x + 4 weight matrices. One launch.
// ---------------------------------------------------------------------------
__global__ __launch_bounds__(256)
void cvt_h_kernel(const float* __restrict__ x,
                  const float* __restrict__ wq, const float* __restrict__ wk,
                  const float* __restrict__ wv, const float* __restrict__ wo)
{
    const int bid = blockIdx.x;
    const float* s; __half* d;
    if (bid < TMAX) {
        s = x + (size_t)bid * NSTATE;
        d = g_xh + (size_t)bid * NSTATE;
    } else {
        const int r = bid - TMAX;
        const int w = r >> 10, row = r & 1023;
        const float* ws = (w == 0) ? wq : (w == 1) ? wk : (w == 2) ? wv : wo;
        __half* ds = (w == 0) ? g_wqh : (w == 1) ? g_wkh : (w == 2) ? g_wvh : g_woh;
        s = ws + (size_t)row * NSTATE;
        d = ds + (size_t)row * NSTATE;
    }
    const int i = threadIdx.x * 4;
    float4 v = *(const float4*)(s + i);
    __half2 h0 = __floats2half2_rn(v.x, v.y);
    __half2 h1 = __floats2half2_rn(v.z, v.w);
    uint2 u; u.x = h2u(h0); u.y = h2u(h1);
    *(uint2*)(d + i) = u;
}

// ---------------------------------------------------------------------------
// fp16 tensor-core GEMM NT: C[M,N] = A[M,K] @ W[N,K]^T (+bias) * scale
// CTA 128x128, BK=32 halves, 8 warps (2x4), warp tile 64x32, mma m16n8k16,
// cp.async double-buffered. OUTH: output __half2, else float2.
// ---------------------------------------------------------------------------
#define HSTR 40                  // halves per smem row (80 B, conflict-free)
#define HB32 (HSTR / 2)          // b32 per smem row
#define HBUF (128 * HSTR)        // halves per tile
#define HBUF_B (HBUF * 2)        // bytes per tile (10240)

__device__ __forceinline__ void cp16(uint32_t dst, const void* src) {
    asm volatile("cp.async.cg.shared.global [%0], [%1], 16;\n"
                 :: "r"(dst), "l"(src));
}

template<bool OUTH>
__device__ __forceinline__ void gemm_h_body(const __half* __restrict__ A,
                                            const __half* __restrict__ W,
                                            const float* __restrict__ bias,
                                            void* __restrict__ Cv, float scale)
{
    __shared__ __half smh[4 * HBUF];     // A0,B0,A1,B1 = 40960 B

    const int tid = threadIdx.x, lane = tid & 31, warp = tid >> 5;
    const int g = lane >> 2, tg = lane & 3;
    const int wm = (warp >> 2) * 64, wn = (warp & 3) * 32;
    const int bm = blockIdx.y * 128, bn = blockIdx.x * 128;
    const uint32_t sbase = (uint32_t)__cvta_generic_to_shared(smh);

    float acc[4][4][4];
#pragma unroll
    for (int a = 0; a < 4; a++)
#pragma unroll
        for (int b = 0; b < 4; b++)
#pragma unroll
            for (int c = 0; c < 4; c++) acc[a][b][c] = 0.f;

    // fill one double-buffer slot: A tile + W tile, 512 x 16B segments
    auto fill = [&](int buf, int kt) {
        const uint32_t off = sbase + (uint32_t)buf * (2u * HBUF_B);
#pragma unroll
        for (int i = 0; i < 2; i++) {
            const int idx = tid + i * 256;
            const int row = idx >> 2, seg = idx & 3;
            const uint32_t d = off + (uint32_t)(row * HSTR + seg * 8) * 2u;
            cp16(d,          A + (size_t)(bm + row) * NSTATE + kt + seg * 8);
            cp16(d + HBUF_B, W + (size_t)(bn + row) * NSTATE + kt + seg * 8);
        }
        asm volatile("cp.async.commit_group;\n");
    };

    const int T = NSTATE / 32;    // 32 chunks
    fill(0, 0);

    for (int t = 0; t < T; t++) {
        if (t + 1 < T) {
            fill((t + 1) & 1, (t + 1) * 32);
            asm volatile("cp.async.wait_group 1;\n" ::: "memory");
        } else {
            asm volatile("cp.async.wait_group 0;\n" ::: "memory");
        }
        __syncthreads();

        const uint32_t* A32 = (const uint32_t*)(smh + (t & 1) * 2 * HBUF);
        const uint32_t* B32 = A32 + HBUF / 2;

#pragma unroll
        for (int ks = 0; ks < 2; ks++) {
            unsigned af[4][4], bf[4][2];
#pragma unroll
            for (int mt = 0; mt < 4; mt++) {
                const int base = (wm + mt * 16 + g) * HB32 + ks * 8 + tg;
                af[mt][0] = A32[base];
                af[mt][1] = A32[base + 8 * HB32];
                af[mt][2] = A32[base + 4];
                af[mt][3] = A32[base + 8 * HB32 + 4];
            }
#pragma unroll
            for (int nt = 0; nt < 4; nt++) {
                const int base = (wn + nt * 8 + g) * HB32 + ks * 8 + tg;
                bf[nt][0] = B32[base];
                bf[nt][1] = B32[base + 4];
            }
#pragma unroll
            for (int mt = 0; mt < 4; mt++)
#pragma unroll
                for (int nt = 0; nt < 4; nt++)
                    asm volatile(
                        "mma.sync.aligned.m16n8k16.row.col.f32.f16.f16.f32 "
                        "{%0,%1,%2,%3}, {%4,%5,%6,%7}, {%8,%9}, {%0,%1,%2,%3};\n"
                        : "+f"(acc[mt][nt][0]), "+f"(acc[mt][nt][1]),
                          "+f"(acc[mt][nt][2]), "+f"(acc[mt][nt][3])
                        : "r"(af[mt][0]), "r"(af[mt][1]),
                          "r"(af[mt][2]), "r"(af[mt][3]),
                          "r"(bf[nt][0]), "r"(bf[nt][1]));
        }
        __syncthreads();
    }

#pragma unroll
    for (int nt = 0; nt < 4; nt++) {
        const int col = bn + wn + nt * 8 + 2 * tg;
        float b0 = 0.f, b1 = 0.f;
        if (bias) { b0 = bias[col]; b1 = bias[col + 1]; }
#pragma unroll
        for (int mt = 0; mt < 4; mt++) {
            const int row = bm + wm + mt * 16 + g;
            const float v0 = (acc[mt][nt][0] + b0) * scale;
            const float v1 = (acc[mt][nt][1] + b1) * scale;
            const float v2 = (acc[mt][nt][2] + b0) * scale;
            const float v3 = (acc[mt][nt][3] + b1) * scale;
            if (OUTH) {
                __half* Ch = (__half*)Cv;
                *(__half2*)&Ch[(size_t)row * NSTATE + col]       = __floats2half2_rn(v0, v1);
                *(__half2*)&Ch[(size_t)(row + 8) * NSTATE + col] = __floats2half2_rn(v2, v3);
            } else {
                float* Cf = (float*)Cv;
                *(float2*)&Cf[(size_t)row * NSTATE + col]       = make_float2(v0, v1);
                *(float2*)&Cf[(size_t)(row + 8) * NSTATE + col] = make_float2(v2, v3);
            }
        }
    }
}

__global__ __launch_bounds__(256)
void qkv_h_kernel(const float* __restrict__ bq, const float* __restrict__ bv)
{
    if (blockIdx.z == 0)
        gemm_h_body<true>(g_xh, g_wqh, bq,      g_qh, QSCALE);  // scale folded in
    else if (blockIdx.z == 1)
        gemm_h_body<true>(g_xh, g_wkh, nullptr, g_kh, 1.f);
    else
        gemm_h_body<true>(g_xh, g_wvh, bv,      g_vh, 1.f);
}

__global__ __launch_bounds__(256)
void oproj_h_kernel(const float* __restrict__ bo, float* __restrict__ out)
{
    gemm_h_body<false>(g_ctxh, g_woh, bo, out, 1.f);
}

// ---------------------------------------------------------------------------
// Flash attention, fp16 mma.m16n8k16 + FMA-only exp2 softmax (log2 domain).
// CTA: 64 queries x 1 head, 4 warps x 16 rows. P stays in registers (FA2).
// smem strides: 72 halves (36 b32) -> conflict-free frag LDS.
// ---------------------------------------------------------------------------
#define ATS 72     // halves per row
#define AT32 (ATS / 2)

__global__ __launch_bounds__(128)
void attn_h_kernel(const int* __restrict__ cu, int nseq)
{
    __shared__ __half Qs[64 * ATS];
    __shared__ __half Ks[64 * ATS];
    __shared__ __half Vt[64 * ATS];   // transposed: Vt[dim][key]

    const int h = blockIdx.y;

    int s0 = 0, L = 0, q0 = 0, found = 0;
    {
        int acct = 0;
        const int gt = blockIdx.x;
        for (int b = 0; b < nseq; b++) {
            const int s = cu[b], e = cu[b + 1];
            const int Lb = e - s;
            const int nt = (Lb + 63) >> 6;
            if (gt < acct + nt) { s0 = s; L = Lb; q0 = s + (gt - acct) * 64; found = 1; break; }
            acct += nt;
        }
    }
    if (!found) return;

    const int tid = threadIdx.x, lane = tid & 31, warp = tid >> 5;
    const int g = lane >> 2, tg = lane & 3;
    const int qrow0 = warp * 16;
    const int qrows = min(64, s0 + L - q0);

    // Q fill (g_qh is pre-scaled by QSCALE)
#pragma unroll
    for (int it = 0; it < 4; it++) {
        const int idx = tid + it * 128;
        const int r = idx >> 3, c8 = (idx & 7) * 8;
        int4 v = make_int4(0, 0, 0, 0);
        if (r < qrows)
            v = *(const int4*)&g_qh[(size_t)(q0 + r) * NSTATE + h * HDIM + c8];
        *(int4*)&Qs[r * ATS + c8] = v;
    }
    __syncthreads();

    // Q fragments register-resident
    const uint32_t* Q32 = (const uint32_t*)Qs;
    unsigned qf[4][4];
#pragma unroll
    for (int ks = 0; ks < 4; ks++) {
        const int base = (qrow0 + g) * AT32 + ks * 8 + tg;
        qf[ks][0] = Q32[base];
        qf[ks][1] = Q32[base + 8 * AT32];
        qf[ks][2] = Q32[base + 4];
        qf[ks][3] = Q32[base + 8 * AT32 + 4];
    }

    float m0 = -1e30f, m1 = -1e30f, l0 = 0.f, l1 = 0.f;
    float o[8][4];
#pragma unroll
    for (int nt = 0; nt < 8; nt++)
#pragma unroll
        for (int j = 0; j < 4; j++) o[nt][j] = 0.f;

    const uint32_t* K32 = (const uint32_t*)Ks;
    const uint32_t* V32 = (const uint32_t*)Vt;

    const int nkt = (L + 63) >> 6;
    for (int kt = 0; kt < nkt; kt++) {
        const int kbase = kt * 64;
        const int kc = min(64, L - kbase);

        __syncthreads();   // protect prev Ks/Vt reads
#pragma unroll
        for (int it = 0; it < 4; it++) {
            const int idx = tid + it * 128;
            const int r = idx >> 3, c8 = (idx & 7) * 8;
            int4 kv = make_int4(0, 0, 0, 0);
            int4 vv = make_int4(0, 0, 0, 0);
            if (r < kc) {
                const size_t go = (size_t)(s0 + kbase + r) * NSTATE + h * HDIM + c8;
                kv = *(const int4*)&g_kh[go];
                vv = *(const int4*)&g_vh[go];
            }
            *(int4*)&Ks[r * ATS + c8] = kv;
            union { int4 i4; __half hh[8]; } u; u.i4 = vv;
#pragma unroll
            for (int j = 0; j < 8; j++) Vt[(c8 + j) * ATS + r] = u.hh[j];
        }
        __syncthreads();

        // S = Q @ K^T (log2 domain; scale folded into Q)
        float s[8][4];
#pragma unroll
        for (int nt = 0; nt < 8; nt++)
#pragma unroll
            for (int j = 0; j < 4; j++) s[nt][j] = 0.f;

#pragma unroll
        for (int ks = 0; ks < 4; ks++) {
#pragma unroll
            for (int nt = 0; nt < 8; nt++) {
                const int base = (nt * 8 + g) * AT32 + ks * 8 + tg;
                const unsigned b0 = K32[base];
                const unsigned b1 = K32[base + 4];
                asm volatile(
                    "mma.sync.aligned.m16n8k16.row.col.f32.f16.f16.f32 "
                    "{%0,%1,%2,%3}, {%4,%5,%6,%7}, {%8,%9}, {%0,%1,%2,%3};\n"
                    : "+f"(s[nt][0]), "+f"(s[nt][1]), "+f"(s[nt][2]), "+f"(s[nt][3])
                    : "r"(qf[ks][0]), "r"(qf[ks][1]), "r"(qf[ks][2]), "r"(qf[ks][3]),
                      "r"(b0), "r"(b1));
            }
        }

        if (kc < 64) {
#pragma unroll
            for (int nt = 0; nt < 8; nt++) {
                const int c = nt * 8 + 2 * tg;
                if (c >= kc)     { s[nt][0] = -1e30f; s[nt][2] = -1e30f; }
                if (c + 1 >= kc) { s[nt][1] = -1e30f; s[nt][3] = -1e30f; }
            }
        }

        // online softmax (c0,c1 = row g; c2,c3 = row g+8)
        float mt0 = -1e30f, mt1 = -1e30f;
#pragma unroll
        for (int nt = 0; nt < 8; nt++) {
            mt0 = fmaxf(mt0, fmaxf(s[nt][0], s[nt][1]));
            mt1 = fmaxf(mt1, fmaxf(s[nt][2], s[nt][3]));
        }
        mt0 = fmaxf(mt0, __shfl_xor_sync(0xffffffffu, mt0, 1));
        mt0 = fmaxf(mt0, __shfl_xor_sync(0xffffffffu, mt0, 2));
        mt1 = fmaxf(mt1, __shfl_xor_sync(0xffffffffu, mt1, 1));
        mt1 = fmaxf(mt1, __shfl_xor_sync(0xffffffffu, mt1, 2));

        const float mn0 = fmaxf(m0, mt0), mn1 = fmaxf(m1, mt1);
        const float a0 = exp2f_fast(m0 - mn0), a1 = exp2f_fast(m1 - mn1);

        // P in fp16 registers; l summed from the ROUNDED values
        unsigned ph0[8], ph1[8];
        float r0 = 0.f, r1 = 0.f;
#pragma unroll
        for (int nt = 0; nt < 8; nt++) {
            const float e0 = exp2f_fast(s[nt][0] - mn0);
            const float e1 = exp2f_fast(s[nt][1] - mn0);
            const float e2 = exp2f_fast(s[nt][2] - mn1);
            const float e3 = exp2f_fast(s[nt][3] - mn1);
            __half2 hA = __floats2half2_rn(e0, e1);
            __half2 hB = __floats2half2_rn(e2, e3);
            float2 fA = __half22float2(hA);
            float2 fB = __half22float2(hB);
            r0 += fA.x + fA.y;
            r1 += fB.x + fB.y;
            ph0[nt] = h2u(hA);
            ph1[nt] = h2u(hB);
        }
        r0 += __shfl_xor_sync(0xffffffffu, r0, 1);
        r0 += __shfl_xor_sync(0xffffffffu, r0, 2);
        r1 += __shfl_xor_sync(0xffffffffu, r1, 1);
        r1 += __shfl_xor_sync(0xffffffffu, r1, 2);
        l0 = l0 * a0 + r0; l1 = l1 * a1 + r1;
        m0 = mn0; m1 = mn1;
#pragma unroll
        for (int nt = 0; nt < 8; nt++) {
            o[nt][0] *= a0; o[nt][1] *= a0;
            o[nt][2] *= a1; o[nt][3] *= a1;
        }

        // O += P @ V  — P fragments come straight from the S C-fragments
#pragma unroll
        for (int ks = 0; ks < 4; ks++) {
            const unsigned pa0 = ph0[2 * ks],     pa1 = ph1[2 * ks];
            const unsigned pa2 = ph0[2 * ks + 1], pa3 = ph1[2 * ks + 1];
#pragma unroll
            for (int nt = 0; nt < 8; nt++) {
                const int base = (nt * 8 + g) * AT32 + ks * 8 + tg;
                const unsigned b0 = V32[base];
                const unsigned b1 = V32[base + 4];
                asm volatile(
                    "mma.sync.aligned.m16n8k16.row.col.f32.f16.f16.f32 "
                    "{%0,%1,%2,%3}, {%4,%5,%6,%7}, {%8,%9}, {%0,%1,%2,%3};\n"
                    : "+f"(o[nt][0]), "+f"(o[nt][1]), "+f"(o[nt][2]), "+f"(o[nt][3])
                    : "r"(pa0), "r"(pa1), "r"(pa2), "r"(pa3),
                      "r"(b0), "r"(b1));
            }
        }
    }

    // normalize + write ctx (fp16)
    const float il0 = 1.f / l0, il1 = 1.f / l1;
    const int r0g = qrow0 + g, r1g = r0g + 8;
#pragma unroll
    for (int nt = 0; nt < 8; nt++) {
        const int c = nt * 8 + 2 * tg;
        if (r0g < qrows) {
            __half2 w = __floats2half2_rn(o[nt][0] * il0, o[nt][1] * il0);
            *(__half2*)&g_ctxh[(size_t)(q0 + r0g) * NSTATE + h * HDIM + c] = w;
        }
        if (r1g < qrows) {
            __half2 w = __floats2half2_rn(o[nt][2] * il1, o[nt][3] * il1);
            *(__half2*)&g_ctxh[(size_t)(q0 + r1g) * NSTATE + h * HDIM + c] = w;
        }
    }
}

// ---------------------------------------------------------------------------
// Launch. Inputs: 0=x, 1=cu_seqlens, 2=Wq, 3=bq, 4=Wk, 5=Wv, 6=bv, 7=Wo, 8=bo
// ---------------------------------------------------------------------------
extern "C" void kernel_launch(void* const* d_in, const int* in_sizes, int n_in,
                              void* d_out, int out_size)
{
    const float* x  = (const float*)d_in[0];
    const int*   cu = (const int*)d_in[1];
    const float* Wq = (const float*)d_in[2];
    const float* bq = (const float*)d_in[3];
    const float* Wk = (const float*)d_in[4];
    const float* Wv = (const float*)d_in[5];
    const float* bv = (const float*)d_in[6];
    const float* Wo = (const float*)d_in[7];
    const float* bo = (const float*)d_in[8];

    const int T = in_sizes[0] / NSTATE;       // 6144
    const int nseq = in_sizes[1] - 1;         // 8

    cvt_h_kernel<<<TMAX + 4 * NSTATE, 256>>>(x, Wq, Wk, Wv, Wo);

    dim3 gqkv(NSTATE / 128, T / 128, 3);
    qkv_h_kernel<<<gqkv, 256>>>(bq, bv);

    const int maxTiles = T / 64 + nseq;
    dim3 gattn(maxTiles, NHEAD);
    attn_h_kernel<<<gattn, 128>>>(cu, nseq);

    dim3 go(NSTATE / 128, T / 128);
    oproj_h_kernel<<<go, 256>>>(bo, (float*)d_out);
}

// round 7
// speedup vs baseline: 5.9117x; 1.2371x over previous
#include <cuda_runtime.h>
#include <cuda_fp16.h>
#include <cstdint>

#define NSTATE 1024
#define NHEAD  16
#define HDIM   64
#define TMAX   6144

// Scratch (device globals: allocation-free rule). All activations in fp16.
__device__ __half g_qh[TMAX * NSTATE];     // pre-scaled by QSCALE
__device__ __half g_kh[TMAX * NSTATE];
__device__ __half g_vh[TMAX * NSTATE];
__device__ __half g_ctxh[TMAX * NSTATE];
__device__ __half g_xh[TMAX * NSTATE];
__device__ __half g_wqh[NSTATE * NSTATE];
__device__ __half g_wkh[NSTATE * NSTATE];
__device__ __half g_wvh[NSTATE * NSTATE];
__device__ __half g_woh[NSTATE * NSTATE];

#define QSCALE (0.125f * 1.44269504088896340736f)   // 1/sqrt(64) * log2(e)

// FMA-only exp2 for y <= 0 (softmax path). |rel err| ~ 2e-6.
__device__ __forceinline__ float exp2f_fast(float y) {
    y = fmaxf(y, -100.f);
    float z = __fadd_rn(y, 12582912.f);
    float r = __fsub_rn(z, 12582912.f);
    float f = y - r;
    int   n = __float_as_int(z) - 0x4B400000;
    float p = 1.3333558e-3f;
    p = fmaf(p, f, 9.6181291e-3f);
    p = fmaf(p, f, 5.5504109e-2f);
    p = fmaf(p, f, 2.4022651e-1f);
    p = fmaf(p, f, 6.9314718e-1f);
    p = fmaf(p, f, 1.0f);
    return __int_as_float(__float_as_int(p) + (n << 23));
}

__device__ __forceinline__ unsigned h2u(__half2 h) {
    return *reinterpret_cast<unsigned*>(&h);
}

__device__ __forceinline__ void ldsm4(unsigned& r0, unsigned& r1,
                                      unsigned& r2, unsigned& r3, uint32_t a) {
    asm volatile("ldmatrix.sync.aligned.m8n8.x4.shared.b16 {%0,%1,%2,%3}, [%4];"
                 : "=r"(r0), "=r"(r1), "=r"(r2), "=r"(r3) : "r"(a));
}
__device__ __forceinline__ void ldsm4t(unsigned& r0, unsigned& r1,
                                       unsigned& r2, unsigned& r3, uint32_t a) {
    asm volatile("ldmatrix.sync.aligned.m8n8.x4.trans.shared.b16 {%0,%1,%2,%3}, [%4];"
                 : "=r"(r0), "=r"(r1), "=r"(r2), "=r"(r3) : "r"(a));
}
#define MMA16816(d0,d1,d2,d3,a0,a1,a2,a3,b0,b1)                            \
    asm volatile(                                                          \
        "mma.sync.aligned.m16n8k16.row.col.f32.f16.f16.f32 "               \
        "{%0,%1,%2,%3}, {%4,%5,%6,%7}, {%8,%9}, {%0,%1,%2,%3};\n"          \
        : "+f"(d0), "+f"(d1), "+f"(d2), "+f"(d3)                           \
        : "r"(a0), "r"(a1), "r"(a2), "r"(a3), "r"(b0), "r"(b1))

// ---------------------------------------------------------------------------
// Fused fp32 -> fp16 conversion of x + 4 weight matrices. One launch.
// ---------------------------------------------------------------------------
__global__ __launch_bounds__(256)
void cvt_h_kernel(const float* __restrict__ x,
                  const float* __restrict__ wq, const float* __restrict__ wk,
                  const float* __restrict__ wv, const float* __restrict__ wo)
{
    const int bid = blockIdx.x;
    const float* s; __half* d;
    if (bid < TMAX) {
        s = x + (size_t)bid * NSTATE;
        d = g_xh + (size_t)bid * NSTATE;
    } else {
        const int r = bid - TMAX;
        const int w = r >> 10, row = r & 1023;
        const float* ws = (w == 0) ? wq : (w == 1) ? wk : (w == 2) ? wv : wo;
        __half* ds = (w == 0) ? g_wqh : (w == 1) ? g_wkh : (w == 2) ? g_wvh : g_woh;
        s = ws + (size_t)row * NSTATE;
        d = ds + (size_t)row * NSTATE;
    }
    const int i = threadIdx.x * 4;
    float4 v = *(const float4*)(s + i);
    __half2 h0 = __floats2half2_rn(v.x, v.y);
    __half2 h1 = __floats2half2_rn(v.z, v.w);
    uint2 u; u.x = h2u(h0); u.y = h2u(h1);
    *(uint2*)(d + i) = u;
}

// ---------------------------------------------------------------------------
// fp16 tensor-core GEMM NT: C[M,N] = A[M,K] @ W[N,K]^T (+bias) * scale
// CTA 128x128, BK=32, 8 warps (2x4), warp 64x32, mma m16n8k16,
// 3-stage cp.async pipeline, ldmatrix.x4 fragment loads.
// ---------------------------------------------------------------------------
#define HSTR 40                  // halves per smem row (80 B, conflict-free)
#define HBUF (128 * HSTR)        // halves per tile
#define HBUF_B (HBUF * 2)        // bytes per tile (10240)
#define GEMM_SMEM (3 * 2 * HBUF_B)   // 61440 B (3 stages x [A,W])
#define NCH (NSTATE / 32)        // 32 k-chunks

__device__ __forceinline__ void cp16(uint32_t dst, const void* src) {
    asm volatile("cp.async.cg.shared.global [%0], [%1], 16;\n"
                 :: "r"(dst), "l"(src));
}

template<bool OUTH>
__device__ __forceinline__ void gemm_h_body(const __half* __restrict__ A,
                                            const __half* __restrict__ W,
                                            const float* __restrict__ bias,
                                            void* __restrict__ Cv, float scale)
{
    extern __shared__ __half smh[];

    const int tid = threadIdx.x, lane = tid & 31, warp = tid >> 5;
    const int g = lane >> 2, tg = lane & 3;
    const int wm = (warp >> 2) * 64, wn = (warp & 3) * 32;
    const int bm = blockIdx.y * 128, bn = blockIdx.x * 128;
    const uint32_t sbase = (uint32_t)__cvta_generic_to_shared(smh);

    // ldmatrix per-lane offsets. sel = lane>>3.
    const int sel = lane >> 3;
    const int a_r = (lane & 7) + (sel & 1) * 8;   // A: tiles (r0,k0),(r8,k0),(r0,k8),(r8,k8)
    const int a_c = (sel >> 1) * 8;
    const int b_r = (lane & 7) + (sel >> 1) * 8;  // B: tiles (n0,k0),(n0,k8),(n8,k0),(n8,k8)
    const int b_c = (sel & 1) * 8;

    float acc[4][4][4];
#pragma unroll
    for (int a = 0; a < 4; a++)
#pragma unroll
        for (int b = 0; b < 4; b++)
#pragma unroll
            for (int c = 0; c < 4; c++) acc[a][b][c] = 0.f;

    auto fill = [&](int stage, int kt) {
        const uint32_t off = sbase + (uint32_t)stage * (2u * HBUF_B);
#pragma unroll
        for (int i = 0; i < 2; i++) {
            const int idx = tid + i * 256;
            const int row = idx >> 2, seg = idx & 3;
            const uint32_t d = off + (uint32_t)(row * HSTR + seg * 8) * 2u;
            cp16(d,          A + (size_t)(bm + row) * NSTATE + kt + seg * 8);
            cp16(d + HBUF_B, W + (size_t)(bn + row) * NSTATE + kt + seg * 8);
        }
        asm volatile("cp.async.commit_group;\n");
    };

    fill(0, 0);
    fill(1, 32);

    for (int t = 0; t < NCH; t++) {
        if (t < NCH - 1) asm volatile("cp.async.wait_group 1;\n" ::: "memory");
        else             asm volatile("cp.async.wait_group 0;\n" ::: "memory");
        __syncthreads();                    // stage t visible; stage t-1 reads done

        if (t + 2 < NCH) fill((t + 2) % 3, (t + 2) * 32);

        const uint32_t sb = sbase + (uint32_t)(t % 3) * (2u * HBUF_B);

#pragma unroll
        for (int ks = 0; ks < 2; ks++) {
            unsigned af[4][4], bf[4][2];
#pragma unroll
            for (int mt = 0; mt < 4; mt++)
                ldsm4(af[mt][0], af[mt][1], af[mt][2], af[mt][3],
                      sb + (uint32_t)((wm + mt * 16 + a_r) * HSTR + ks * 16 + a_c) * 2u);
#pragma unroll
            for (int np = 0; np < 2; np++)
                ldsm4(bf[2 * np][0], bf[2 * np][1], bf[2 * np + 1][0], bf[2 * np + 1][1],
                      sb + HBUF_B +
                      (uint32_t)((wn + np * 16 + b_r) * HSTR + ks * 16 + b_c) * 2u);
#pragma unroll
            for (int mt = 0; mt < 4; mt++)
#pragma unroll
                for (int nt = 0; nt < 4; nt++)
                    MMA16816(acc[mt][nt][0], acc[mt][nt][1],
                             acc[mt][nt][2], acc[mt][nt][3],
                             af[mt][0], af[mt][1], af[mt][2], af[mt][3],
                             bf[nt][0], bf[nt][1]);
        }
    }

#pragma unroll
    for (int nt = 0; nt < 4; nt++) {
        const int col = bn + wn + nt * 8 + 2 * tg;
        float b0 = 0.f, b1 = 0.f;
        if (bias) { b0 = bias[col]; b1 = bias[col + 1]; }
#pragma unroll
        for (int mt = 0; mt < 4; mt++) {
            const int row = bm + wm + mt * 16 + g;
            const float v0 = (acc[mt][nt][0] + b0) * scale;
            const float v1 = (acc[mt][nt][1] + b1) * scale;
            const float v2 = (acc[mt][nt][2] + b0) * scale;
            const float v3 = (acc[mt][nt][3] + b1) * scale;
            if (OUTH) {
                __half* Ch = (__half*)Cv;
                *(__half2*)&Ch[(size_t)row * NSTATE + col]       = __floats2half2_rn(v0, v1);
                *(__half2*)&Ch[(size_t)(row + 8) * NSTATE + col] = __floats2half2_rn(v2, v3);
            } else {
                float* Cf = (float*)Cv;
                *(float2*)&Cf[(size_t)row * NSTATE + col]       = make_float2(v0, v1);
                *(float2*)&Cf[(size_t)(row + 8) * NSTATE + col] = make_float2(v2, v3);
            }
        }
    }
}

__global__ __launch_bounds__(256)
void qkv_h_kernel(const float* __restrict__ bq, const float* __restrict__ bv)
{
    if (blockIdx.z == 0)
        gemm_h_body<true>(g_xh, g_wqh, bq,      g_qh, QSCALE);
    else if (blockIdx.z == 1)
        gemm_h_body<true>(g_xh, g_wkh, nullptr, g_kh, 1.f);
    else
        gemm_h_body<true>(g_xh, g_wvh, bv,      g_vh, 1.f);
}

__global__ __launch_bounds__(256)
void oproj_h_kernel(const float* __restrict__ bo, float* __restrict__ out)
{
    gemm_h_body<false>(g_ctxh, g_woh, bo, out, 1.f);
}

// ---------------------------------------------------------------------------
// Flash attention, fp16 m16n8k16 + FMA exp2 (log2 domain), FA2 register P.
// K frags via ldmatrix.x4, V frags via ldmatrix.x4.trans (no manual transpose).
// CTA: 64 queries x 1 head, 4 warps x 16 rows. smem stride 72 halves.
// ---------------------------------------------------------------------------
#define ATS 72
#define AT32 (ATS / 2)

__global__ __launch_bounds__(128)
void attn_h_kernel(const int* __restrict__ cu, int nseq)
{
    __shared__ __half Qs[64 * ATS];
    __shared__ __half Ks[64 * ATS];
    __shared__ __half Vs[64 * ATS];   // natural layout [key][dim]

    const int h = blockIdx.y;

    int s0 = 0, L = 0, q0 = 0, found = 0;
    {
        int acct = 0;
        const int gt = blockIdx.x;
        for (int b = 0; b < nseq; b++) {
            const int s = cu[b], e = cu[b + 1];
            const int Lb = e - s;
            const int nt = (Lb + 63) >> 6;
            if (gt < acct + nt) { s0 = s; L = Lb; q0 = s + (gt - acct) * 64; found = 1; break; }
            acct += nt;
        }
    }
    if (!found) return;

    const int tid = threadIdx.x, lane = tid & 31, warp = tid >> 5;
    const int g = lane >> 2, tg = lane & 3;
    const int qrow0 = warp * 16;
    const int qrows = min(64, s0 + L - q0);

    const uint32_t ksb = (uint32_t)__cvta_generic_to_shared(Ks);
    const uint32_t vsb = (uint32_t)__cvta_generic_to_shared(Vs);
    const int sel = lane >> 3;
    // K (non-trans): tiles (n0,k0),(n0,k8),(n8,k0),(n8,k8)
    const int kb_r = (lane & 7) + (sel >> 1) * 8;
    const int kb_c = (sel & 1) * 8;
    // V (trans): tiles (k0,n0),(k8,n0),(k0,n8),(k8,n8)
    const int vb_r = (lane & 7) + (sel & 1) * 8;
    const int vb_c = (sel >> 1) * 8;

    // Q fill (g_qh is pre-scaled by QSCALE)
#pragma unroll
    for (int it = 0; it < 4; it++) {
        const int idx = tid + it * 128;
        const int r = idx >> 3, c8 = (idx & 7) * 8;
        int4 v = make_int4(0, 0, 0, 0);
        if (r < qrows)
            v = *(const int4*)&g_qh[(size_t)(q0 + r) * NSTATE + h * HDIM + c8];
        *(int4*)&Qs[r * ATS + c8] = v;
    }
    __syncthreads();

    const uint32_t* Q32 = (const uint32_t*)Qs;
    unsigned qf[4][4];
#pragma unroll
    for (int ks = 0; ks < 4; ks++) {
        const int base = (qrow0 + g) * AT32 + ks * 8 + tg;
        qf[ks][0] = Q32[base];
        qf[ks][1] = Q32[base + 8 * AT32];
        qf[ks][2] = Q32[base + 4];
        qf[ks][3] = Q32[base + 8 * AT32 + 4];
    }

    float m0 = -1e30f, m1 = -1e30f, l0 = 0.f, l1 = 0.f;
    float o[8][4];
#pragma unroll
    for (int nt = 0; nt < 8; nt++)
#pragma unroll
        for (int j = 0; j < 4; j++) o[nt][j] = 0.f;

    const int nkt = (L + 63) >> 6;
    for (int kt = 0; kt < nkt; kt++) {
        const int kbase = kt * 64;
        const int kc = min(64, L - kbase);

        __syncthreads();   // protect prev Ks/Vs reads
#pragma unroll
        for (int it = 0; it < 4; it++) {
            const int idx = tid + it * 128;
            const int r = idx >> 3, c8 = (idx & 7) * 8;
            int4 kv = make_int4(0, 0, 0, 0);
            int4 vv = make_int4(0, 0, 0, 0);
            if (r < kc) {
                const size_t go = (size_t)(s0 + kbase + r) * NSTATE + h * HDIM + c8;
                kv = *(const int4*)&g_kh[go];
                vv = *(const int4*)&g_vh[go];
            }
            *(int4*)&Ks[r * ATS + c8] = kv;
            *(int4*)&Vs[r * ATS + c8] = vv;
        }
        __syncthreads();

        // S = Q @ K^T (log2 domain; scale folded into Q)
        float s[8][4];
#pragma unroll
        for (int nt = 0; nt < 8; nt++)
#pragma unroll
            for (int j = 0; j < 4; j++) s[nt][j] = 0.f;

#pragma unroll
        for (int ks = 0; ks < 4; ks++) {
            unsigned bk[8][2];
#pragma unroll
            for (int np = 0; np < 4; np++)
                ldsm4(bk[2 * np][0], bk[2 * np][1],
                      bk[2 * np + 1][0], bk[2 * np + 1][1],
                      ksb + (uint32_t)((np * 16 + kb_r) * ATS + ks * 16 + kb_c) * 2u);
#pragma unroll
            for (int nt = 0; nt < 8; nt++)
                MMA16816(s[nt][0], s[nt][1], s[nt][2], s[nt][3],
                         qf[ks][0], qf[ks][1], qf[ks][2], qf[ks][3],
                         bk[nt][0], bk[nt][1]);
        }

        if (kc < 64) {
#pragma unroll
            for (int nt = 0; nt < 8; nt++) {
                const int c = nt * 8 + 2 * tg;
                if (c >= kc)     { s[nt][0] = -1e30f; s[nt][2] = -1e30f; }
                if (c + 1 >= kc) { s[nt][1] = -1e30f; s[nt][3] = -1e30f; }
            }
        }

        // online softmax (c0,c1 = row g; c2,c3 = row g+8)
        float mt0 = -1e30f, mt1 = -1e30f;
#pragma unroll
        for (int nt = 0; nt < 8; nt++) {
            mt0 = fmaxf(mt0, fmaxf(s[nt][0], s[nt][1]));
            mt1 = fmaxf(mt1, fmaxf(s[nt][2], s[nt][3]));
        }
        mt0 = fmaxf(mt0, __shfl_xor_sync(0xffffffffu, mt0, 1));
        mt0 = fmaxf(mt0, __shfl_xor_sync(0xffffffffu, mt0, 2));
        mt1 = fmaxf(mt1, __shfl_xor_sync(0xffffffffu, mt1, 1));
        mt1 = fmaxf(mt1, __shfl_xor_sync(0xffffffffu, mt1, 2));

        const float mn0 = fmaxf(m0, mt0), mn1 = fmaxf(m1, mt1);
        const float a0 = exp2f_fast(m0 - mn0), a1 = exp2f_fast(m1 - mn1);

        unsigned ph0[8], ph1[8];
        float r0 = 0.f, r1 = 0.f;
#pragma unroll
        for (int nt = 0; nt < 8; nt++) {
            const float e0 = exp2f_fast(s[nt][0] - mn0);
            const float e1 = exp2f_fast(s[nt][1] - mn0);
            const float e2 = exp2f_fast(s[nt][2] - mn1);
            const float e3 = exp2f_fast(s[nt][3] - mn1);
            __half2 hA = __floats2half2_rn(e0, e1);
            __half2 hB = __floats2half2_rn(e2, e3);
            float2 fA = __half22float2(hA);
            float2 fB = __half22float2(hB);
            r0 += fA.x + fA.y;
            r1 += fB.x + fB.y;
            ph0[nt] = h2u(hA);
            ph1[nt] = h2u(hB);
        }
        r0 += __shfl_xor_sync(0xffffffffu, r0, 1);
        r0 += __shfl_xor_sync(0xffffffffu, r0, 2);
        r1 += __shfl_xor_sync(0xffffffffu, r1, 1);
        r1 += __shfl_xor_sync(0xffffffffu, r1, 2);
        l0 = l0 * a0 + r0; l1 = l1 * a1 + r1;
        m0 = mn0; m1 = mn1;
#pragma unroll
        for (int nt = 0; nt < 8; nt++) {
            o[nt][0] *= a0; o[nt][1] *= a0;
            o[nt][2] *= a1; o[nt][3] *= a1;
        }

        // O += P @ V  — P frags from S C-fragments; V frags via ldmatrix.trans
#pragma unroll
        for (int ks = 0; ks < 4; ks++) {
            const unsigned pa0 = ph0[2 * ks],     pa1 = ph1[2 * ks];
            const unsigned pa2 = ph0[2 * ks + 1], pa3 = ph1[2 * ks + 1];
            unsigned bv[8][2];
#pragma unroll
            for (int np = 0; np < 4; np++)
                ldsm4t(bv[2 * np][0], bv[2 * np][1],
                       bv[2 * np + 1][0], bv[2 * np + 1][1],
                       vsb + (uint32_t)((ks * 16 + vb_r) * ATS + np * 16 + vb_c) * 2u);
#pragma unroll
            for (int nt = 0; nt < 8; nt++)
                MMA16816(o[nt][0], o[nt][1], o[nt][2], o[nt][3],
                         pa0, pa1, pa2, pa3, bv[nt][0], bv[nt][1]);
        }
    }

    // normalize + write ctx (fp16)
    const float il0 = 1.f / l0, il1 = 1.f / l1;
    const int r0g = qrow0 + g, r1g = r0g + 8;
#pragma unroll
    for (int nt = 0; nt < 8; nt++) {
        const int c = nt * 8 + 2 * tg;
        if (r0g < qrows) {
            __half2 w = __floats2half2_rn(o[nt][0] * il0, o[nt][1] * il0);
            *(__half2*)&g_ctxh[(size_t)(q0 + r0g) * NSTATE + h * HDIM + c] = w;
        }
        if (r1g < qrows) {
            __half2 w = __floats2half2_rn(o[nt][2] * il1, o[nt][3] * il1);
            *(__half2*)&g_ctxh[(size_t)(q0 + r1g) * NSTATE + h * HDIM + c] = w;
        }
    }
}

// ---------------------------------------------------------------------------
// Launch. Inputs: 0=x, 1=cu_seqlens, 2=Wq, 3=bq, 4=Wk, 5=Wv, 6=bv, 7=Wo, 8=bo
// ---------------------------------------------------------------------------
extern "C" void kernel_launch(void* const* d_in, const int* in_sizes, int n_in,
                              void* d_out, int out_size)
{
    const float* x  = (const float*)d_in[0];
    const int*   cu = (const int*)d_in[1];
    const float* Wq = (const float*)d_in[2];
    const float* bq = (const float*)d_in[3];
    const float* Wk = (const float*)d_in[4];
    const float* Wv = (const float*)d_in[5];
    const float* bv = (const float*)d_in[6];
    const float* Wo = (const float*)d_in[7];
    const float* bo = (const float*)d_in[8];

    const int T = in_sizes[0] / NSTATE;       // 6144
    const int nseq = in_sizes[1] - 1;         // 8

    cudaFuncSetAttribute(qkv_h_kernel,
                         cudaFuncAttributeMaxDynamicSharedMemorySize, GEMM_SMEM);
    cudaFuncSetAttribute(oproj_h_kernel,
                         cudaFuncAttributeMaxDynamicSharedMemorySize, GEMM_SMEM);

    cvt_h_kernel<<<TMAX + 4 * NSTATE, 256>>>(x, Wq, Wk, Wv, Wo);

    dim3 gqkv(NSTATE / 128, T / 128, 3);
    qkv_h_kernel<<<gqkv, 256, GEMM_SMEM>>>(bq, bv);

    const int maxTiles = T / 64 + nseq;
    dim3 gattn(maxTiles, NHEAD);
    attn_h_kernel<<<gattn, 128>>>(cu, nseq);

    dim3 go(NSTATE / 128, T / 128);
    oproj_h_kernel<<<go, 256, GEMM_SMEM>>>(bo, (float*)d_out);
}